// round 4
// baseline (speedup 1.0000x reference)
#include <cuda_runtime.h>
#include <cuda_bf16.h>
#include <cstdint>

// Problem constants (static in the reference)
#define N_NODES 100000
#define C_CH    32
#define NC      (N_NODES * C_CH)
#define CAP     64          // bucket capacity; deg ~ Poisson(16), P(deg>=64) ~ 1e-19

// Scratch (alloc-free rule: __device__ globals; zero-initialized at module load)
__device__ int   g_cnt[N_NODES];
__device__ int   g_bucket[(size_t)N_NODES * CAP];
__device__ float g_t1[NC];

// ---------------------------------------------------------------------------
// Bin edges by destination: bucket[d][0..deg) = list of sources into d.
// 4 edges per thread: int4 index loads + 4 independent atomics in flight
// (hides the ~318-cycle ATOMG round-trip 4x). Requires g_cnt == 0 on entry
// (initial zero-init; re-zeroed by gather<1>).
// ---------------------------------------------------------------------------
__global__ void bin_kernel(const int* __restrict__ esrc,
                           const int* __restrict__ edst,
                           int E) {
    int base = (blockIdx.x * blockDim.x + threadIdx.x) * 4;
    if (base + 3 < E) {
        int4 s4 = *reinterpret_cast<const int4*>(esrc + base);
        int4 d4 = *reinterpret_cast<const int4*>(edst + base);
        // 4 independent atomics issue back-to-back, then 4 independent stores
        int p0 = atomicAdd(&g_cnt[d4.x], 1);
        int p1 = atomicAdd(&g_cnt[d4.y], 1);
        int p2 = atomicAdd(&g_cnt[d4.z], 1);
        int p3 = atomicAdd(&g_cnt[d4.w], 1);
        if (p0 < CAP) g_bucket[(size_t)d4.x * CAP + p0] = s4.x;
        if (p1 < CAP) g_bucket[(size_t)d4.y * CAP + p1] = s4.y;
        if (p2 < CAP) g_bucket[(size_t)d4.z * CAP + p2] = s4.z;
        if (p3 < CAP) g_bucket[(size_t)d4.w * CAP + p3] = s4.w;
    } else if (base < E) {
        for (int e = base; e < E; e++) {
            int d = __ldg(edst + e);
            int s = __ldg(esrc + e);
            int pos = atomicAdd(&g_cnt[d], 1);
            if (pos < CAP) g_bucket[(size_t)d * CAP + pos] = s;
        }
    }
}

// ---------------------------------------------------------------------------
// Gather pass: one warp per node, lane = channel (32 ch -> 32 lanes).
//   PASS 0: acc = sum_src x[src];  t1 = deg*x - acc;  y = w0*x + w1*t1
//   PASS 1: acc = sum_src t1[src]; y += w2*(deg*t1 - acc); re-zero cnt
// Source selection happens in device code (device-global rule).
// ---------------------------------------------------------------------------
template <int PASS>
__global__ void gather_kernel(const float* __restrict__ x,
                              const float* __restrict__ w,
                              float* __restrict__ y) {
    int gtid = blockIdx.x * blockDim.x + threadIdx.x;
    int node = gtid >> 5;
    int lane = gtid & 31;
    if (node >= N_NODES) return;

    int deg = g_cnt[node];
    const int* __restrict__ bkt = g_bucket + (size_t)node * CAP;
    const float* __restrict__ rows = (PASS == 0) ? x : (const float*)g_t1;

    float acc0 = 0.f, acc1 = 0.f, acc2 = 0.f, acc3 = 0.f;
    float acc4 = 0.f, acc5 = 0.f, acc6 = 0.f, acc7 = 0.f;
    int j = 0;
    int d8 = deg & ~7;
    for (; j < d8; j += 8) {
        // warp-uniform index loads (broadcast), then 8 independent gathers (MLP)
        int s0 = __ldg(bkt + j + 0);
        int s1 = __ldg(bkt + j + 1);
        int s2 = __ldg(bkt + j + 2);
        int s3 = __ldg(bkt + j + 3);
        int s4 = __ldg(bkt + j + 4);
        int s5 = __ldg(bkt + j + 5);
        int s6 = __ldg(bkt + j + 6);
        int s7 = __ldg(bkt + j + 7);
        acc0 += __ldg(rows + (size_t)s0 * C_CH + lane);
        acc1 += __ldg(rows + (size_t)s1 * C_CH + lane);
        acc2 += __ldg(rows + (size_t)s2 * C_CH + lane);
        acc3 += __ldg(rows + (size_t)s3 * C_CH + lane);
        acc4 += __ldg(rows + (size_t)s4 * C_CH + lane);
        acc5 += __ldg(rows + (size_t)s5 * C_CH + lane);
        acc6 += __ldg(rows + (size_t)s6 * C_CH + lane);
        acc7 += __ldg(rows + (size_t)s7 * C_CH + lane);
    }
    for (; j < deg; j++) {
        int s = __ldg(bkt + j);
        acc0 += __ldg(rows + (size_t)s * C_CH + lane);
    }
    float acc = ((acc0 + acc1) + (acc2 + acc3)) + ((acc4 + acc5) + (acc6 + acc7));

    float dg = (float)deg;
    size_t idx = (size_t)node * C_CH + lane;

    if (PASS == 0) {
        float w0 = __ldg(w + 0);
        float w1 = __ldg(w + 1);
        float xv = __ldg(x + idx);
        float t  = dg * xv - acc;
        g_t1[idx] = t;
        y[idx] = w0 * xv + w1 * t;
    } else {
        float w2 = __ldg(w + 2);
        float tv = g_t1[idx];
        float t2 = dg * tv - acc;
        y[idx] += w2 * t2;
        if (lane == 0) g_cnt[node] = 0;   // restore invariant for next call
    }
}

// ---------------------------------------------------------------------------
extern "C" void kernel_launch(void* const* d_in, const int* in_sizes, int n_in,
                              void* d_out, int out_size) {
    const float* x    = (const float*)d_in[0];
    const float* w    = (const float*)d_in[1];
    const int*   esrc = (const int*)d_in[2];
    const int*   edst = (const int*)d_in[3];
    float*       y    = (float*)d_out;
    int E = in_sizes[2];

    const int TPB = 256;
    int bin_blocks    = ((E + 3) / 4 + TPB - 1) / TPB;       // 1563 for E=1.6M
    int gather_blocks = (N_NODES * 32 + TPB - 1) / TPB;      // 12500

    bin_kernel<<<bin_blocks, TPB>>>(esrc, edst, E);
    gather_kernel<0><<<gather_blocks, TPB>>>(x, w, y);
    gather_kernel<1><<<gather_blocks, TPB>>>(x, w, y);
}